// round 9
// baseline (speedup 1.0000x reference)
#include <cuda_runtime.h>
#include <cstdint>

#define DINL __device__ __forceinline__

// ---------------- problem constants ----------------
constexpr int   BHALF = 4096;
constexpr int   NTOT  = 8192;           // 2B rows
constexpr int   DDIM  = 256;            // K
constexpr int   GRID  = 148;            // one exact wave (grid barrier safe)
constexpr int   NGRP  = 296;            // 2 warpgroups per CTA
// alpha = sqrt(log2(e)/T): (a u_i)·(a u_j) = s*log2(e)/T = y, exp(s/T)=2^y
constexpr float ALPHA = 1.6986436f;
constexpr float LN2F  = 0.693147180559945f;

// Per-group SMEM: A double (2x32KB) + B-half double (2x16KB) = 96KB; x2 groups
constexpr int GSM_A0 = 0;
constexpr int GSM_A1 = 32768;
constexpr int GSM_B0 = 65536;
constexpr int GSM_B1 = 81920;
constexpr int GSM_SZ = 98304;
constexpr int SMEM_BYTES = GSM_SZ * 2;   // 196608

// ---------------- device scratch (no allocation allowed) --------------------
__device__ __align__(16) uint8_t g_z[NTOT * DDIM];   // 2 MB, e4m3 (alpha-scaled)
__device__ float g_partial[NTOT];
__device__ float g_pos[NTOT];
__device__ float g_red[64];
__device__ unsigned g_ctr;   // final-reduce counter (reset by prep)
__device__ unsigned g_bar;   // grid barrier counter  (reset by prep)

// ---------------- PTX helpers ----------------
DINL uint32_t smem_u32(const void* p) {
    uint32_t a;
    asm("{ .reg .u64 t; cvta.to.shared.u64 t, %1; cvt.u32.u64 %0, t; }"
        : "=r"(a) : "l"(p));
    return a;
}
DINL float ex2f(float x) { float r; asm("ex2.approx.f32 %0, %1;" : "=f"(r) : "f"(x)); return r; }
DINL float lg2f(float x) { float r; asm("lg2.approx.f32 %0, %1;" : "=f"(r) : "f"(x)); return r; }

DINL void cp_commit() { asm volatile("cp.async.commit_group;" ::: "memory"); }
DINL void cp_wait0()  { asm volatile("cp.async.wait_group 0;" ::: "memory"); }
DINL void grp_bar(int grp) {
    asm volatile("bar.sync %0, 256;" :: "r"(grp + 1) : "memory");
}

DINL void ldsm4(uint32_t& d0, uint32_t& d1, uint32_t& d2, uint32_t& d3, uint32_t addr) {
    asm volatile("ldmatrix.sync.aligned.m8n8.x4.shared.b16 {%0,%1,%2,%3}, [%4];"
                 : "=r"(d0), "=r"(d1), "=r"(d2), "=r"(d3) : "r"(addr));
}
// fp8 e4m3 MMA, K=32, f32 accumulators.
DINL void mma16832(float* c, uint32_t a0, uint32_t a1, uint32_t a2, uint32_t a3,
                   uint32_t b0, uint32_t b1) {
    asm volatile("mma.sync.aligned.m16n8k32.row.col.f32.e4m3.e4m3.f32 "
                 "{%0,%1,%2,%3}, {%4,%5,%6,%7}, {%8,%9}, {%0,%1,%2,%3};"
                 : "+f"(c[0]), "+f"(c[1]), "+f"(c[2]), "+f"(c[3])
                 : "r"(a0), "r"(a1), "r"(a2), "r"(a3), "r"(b0), "r"(b1));
}

// Load a 128x256 fp8 A tile into SMEM, XOR-swizzled; 256 threads (one group).
DINL void load_tile_a(uint32_t dst, int row0, int tg) {
    const char* src = reinterpret_cast<const char*>(g_z) + (size_t)row0 * 256;
    #pragma unroll
    for (int it = 0; it < 8; ++it) {
        int lin = it * 256 + tg;
        int row = lin >> 4;
        int ch  = lin & 15;
        uint32_t sw = (uint32_t)row * 256u + (uint32_t)((ch ^ (row & 7)) << 4);
        const void* gp = src + (size_t)row * 256 + (size_t)ch * 16;
        asm volatile("cp.async.cg.shared.global [%0], [%1], 16;"
                     :: "r"(dst + sw), "l"(gp) : "memory");
    }
}
// Load a 64x256 fp8 B half-tile (16KB); 256 threads (one group).
DINL void load_tile_b(uint32_t dst, int row0, int tg) {
    const char* src = reinterpret_cast<const char*>(g_z) + (size_t)row0 * 256;
    #pragma unroll
    for (int it = 0; it < 4; ++it) {
        int lin = it * 256 + tg;
        int row = lin >> 4;
        int ch  = lin & 15;
        uint32_t sw = (uint32_t)row * 256u + (uint32_t)((ch ^ (row & 7)) << 4);
        const void* gp = src + (size_t)row * 256 + (size_t)ch * 16;
        asm volatile("cp.async.cg.shared.global [%0], [%1], 16;"
                     :: "r"(dst + sw), "l"(gp) : "memory");
    }
}

// ---------------- per half-tile compute: 128x64 mma + exp2 + sums -----------
// 8 warps per group: warp wl -> rows [wl*16, wl*16+16), all 64 cols.
// acc = 32 regs/thread, colp = 16 floats/thread.
DINL void compute_tile(uint32_t a_base, uint32_t b_base, int wl, int lane,
                       bool diag, bool pos, int ib, int jcol0,
                       float& ra0, float& ra1, float* colp) {
    const int mi = lane >> 3, li = lane & 7;
    const int rA = wl * 16 + ((mi & 1) << 3) + li;
    const uint32_t aRow = a_base + (uint32_t)rA * 256u;
    const int axr = rA & 7, acp = mi >> 1;
    const int rBo = ((mi >> 1) << 3) + li;
    const int bcp = mi & 1;

    uint32_t bBase[4];
    int bxr[4];
    #pragma unroll
    for (int jp = 0; jp < 4; ++jp) {
        int r = jp * 16 + rBo;
        bBase[jp] = b_base + (uint32_t)r * 256u;
        bxr[jp] = r & 7;
    }

    float acc[8][4];
    #pragma unroll
    for (int j = 0; j < 8; ++j) {
        acc[j][0] = 0.f; acc[j][1] = 0.f; acc[j][2] = 0.f; acc[j][3] = 0.f;
    }

    #pragma unroll
    for (int s = 0; s < 8; ++s) {          // 8 k-steps of K=32 fp8
        uint32_t a0, a1, a2, a3;
        ldsm4(a0, a1, a2, a3, aRow + (uint32_t)(((s * 2 + acp) ^ axr) << 4));
        #pragma unroll
        for (int jp = 0; jp < 4; ++jp) {
            uint32_t b0, b1, b2, b3;
            ldsm4(b0, b1, b2, b3, bBase[jp] + (uint32_t)(((s * 2 + bcp) ^ bxr[jp]) << 4));
            mma16832(acc[2 * jp],     a0, a1, a2, a3, b0, b1);
            mma16832(acc[2 * jp + 1], a0, a1, a2, a3, b2, b3);
        }
    }

    const int baseRow = wl * 16 + (lane >> 2);   // rows baseRow, baseRow+8
    const int baseCol = (lane & 3) * 2;          // local col (0..63 range)

    if (diag) {
        #pragma unroll
        for (int j = 0; j < 8; ++j) {
            #pragma unroll
            for (int q = 0; q < 4; ++q) {
                int rl = baseRow + ((q & 2) << 2);
                int cl = jcol0 + baseCol + j * 8 + (q & 1);   // col within 128-block
                float e = ex2f(acc[j][q]);
                if (rl == cl) e = 0.f;                        // mask self-sim
                if (q & 2) ra1 += e; else ra0 += e;
            }
        }
    } else {
        #pragma unroll
        for (int k = 0; k < 16; ++k) colp[k] = 0.f;
        #pragma unroll
        for (int j = 0; j < 8; ++j) {
            float e0 = ex2f(acc[j][0]);
            float e1 = ex2f(acc[j][1]);
            float e2 = ex2f(acc[j][2]);
            float e3 = ex2f(acc[j][3]);
            if (pos) {
                int cl0 = jcol0 + baseCol + j * 8;
                int jb = ib + 32;
                if (cl0     == baseRow)     { g_pos[ib*128+baseRow]   = acc[j][0]; g_pos[jb*128+baseRow]   = acc[j][0]; }
                if (cl0 + 1 == baseRow)     { g_pos[ib*128+baseRow]   = acc[j][1]; g_pos[jb*128+baseRow]   = acc[j][1]; }
                if (cl0     == baseRow + 8) { g_pos[ib*128+baseRow+8] = acc[j][2]; g_pos[jb*128+baseRow+8] = acc[j][2]; }
                if (cl0 + 1 == baseRow + 8) { g_pos[ib*128+baseRow+8] = acc[j][3]; g_pos[jb*128+baseRow+8] = acc[j][3]; }
            }
            ra0 += e0 + e1;
            ra1 += e2 + e3;
            colp[j * 2]     += e0 + e2;   // local col baseCol + j*8
            colp[j * 2 + 1] += e1 + e3;   // local col baseCol + j*8 + 1
        }
    }
}

DINL void flush_rows(int rb, int wl, int lane, float& a0, float& a1) {
    float v0 = a0, v1 = a1;
    v0 += __shfl_xor_sync(0xffffffffu, v0, 1);
    v0 += __shfl_xor_sync(0xffffffffu, v0, 2);
    v1 += __shfl_xor_sync(0xffffffffu, v1, 1);
    v1 += __shfl_xor_sync(0xffffffffu, v1, 2);
    if ((lane & 3) == 0) {
        int r = rb * 128 + wl * 16 + (lane >> 2);
        atomicAdd(&g_partial[r],     v0);
        atomicAdd(&g_partial[r + 8], v1);
    }
    a0 = 0.f; a1 = 0.f;
}

// decode (v,k) -> (i,j): virtual row v pairs strip v (64-v tiles) with
// strip 63-v (v+1 tiles): constant 65 tiles per virtual row.
DINL void vk2ij(int v, int k, int& i, int& j) {
    int L = 64 - v;
    if (k < L) { i = v; j = v + k; }
    else       { i = 63 - v; j = i + (k - L); }
}
// flat half-tile index f (0..4159) -> (i, j, h)
DINL void f2ijh(int f, int& i, int& j, int& h) {
    int t = f >> 1;
    h = f & 1;
    vk2ij(t / 65, t % 65, i, j);
}

// ---------------- kernel 1: normalize + pre-scale + e4m3 cast ----------------
__global__ void prep_kernel(const float* __restrict__ xi, const float* __restrict__ xj) {
    const int wid = threadIdx.x >> 5, lane = threadIdx.x & 31;
    const int row = blockIdx.x * 8 + wid;
    const float* x = (row < BHALF) ? (xi + (size_t)row * DDIM)
                                   : (xj + (size_t)(row - BHALF) * DDIM);
    float4 v0 = *reinterpret_cast<const float4*>(x + lane * 8);
    float4 v1 = *reinterpret_cast<const float4*>(x + lane * 8 + 4);
    float s = v0.x*v0.x + v0.y*v0.y + v0.z*v0.z + v0.w*v0.w
            + v1.x*v1.x + v1.y*v1.y + v1.z*v1.z + v1.w*v1.w;
    #pragma unroll
    for (int o = 16; o; o >>= 1) s += __shfl_xor_sync(0xffffffffu, s, o);
    float sc = ALPHA / fmaxf(sqrtf(s), 1e-12f);
    uint16_t p0, p1, p2, p3;
    asm("cvt.rn.satfinite.e4m3x2.f32 %0, %1, %2;" : "=h"(p0) : "f"(v0.y*sc), "f"(v0.x*sc));
    asm("cvt.rn.satfinite.e4m3x2.f32 %0, %1, %2;" : "=h"(p1) : "f"(v0.w*sc), "f"(v0.z*sc));
    asm("cvt.rn.satfinite.e4m3x2.f32 %0, %1, %2;" : "=h"(p2) : "f"(v1.y*sc), "f"(v1.x*sc));
    asm("cvt.rn.satfinite.e4m3x2.f32 %0, %1, %2;" : "=h"(p3) : "f"(v1.w*sc), "f"(v1.z*sc));
    uint2 pk;
    pk.x = (uint32_t)p0 | ((uint32_t)p1 << 16);
    pk.y = (uint32_t)p2 | ((uint32_t)p3 << 16);
    *reinterpret_cast<uint2*>(&g_z[(size_t)row * DDIM + lane * 8]) = pk;
    if (lane == 0) g_partial[row] = 0.f;   // zero accumulators every launch
    if (row == 0 && lane == 1) { g_ctr = 0u; g_bar = 0u; }
}

// ---------------- kernel 2: two independent tile pipelines per CTA ----------
__global__ void __launch_bounds__(512, 1) gemm_kernel(float* __restrict__ out) {
    extern __shared__ char smem[];
    const int tid = threadIdx.x, w = tid >> 5, lane = tid & 31;
    const int grp = w >> 3;            // warpgroup 0 / 1
    const int wl  = w & 7;             // warp within group
    const int tg  = tid & 255;         // thread within group
    const uint32_t gb = smem_u32(smem) + (uint32_t)grp * GSM_SZ;
    const uint32_t Ab[2] = { gb + GSM_A0, gb + GSM_A1 };
    const uint32_t Bb[2] = { gb + GSM_B0, gb + GSM_B1 };

    // contiguous range over 4160 half-tiles: 4160 = 296*14 + 16
    const int g = blockIdx.x * 2 + grp;
    const int start = g * 14 + min(g, 16);
    const int count = 14 + (g < 16 ? 1 : 0);

    int i, j, h;
    f2ijh(start, i, j, h);

    load_tile_a(Ab[0], i * 128, tg);
    load_tile_b(Bb[0], j * 128 + h * 64, tg);
    cp_commit();
    cp_wait0();
    grp_bar(grp);

    float ra0 = 0.f, ra1 = 0.f;
    float colp[16];
    int abuf = 0, bbuf = 0;

    for (int n = 0; n < count; ++n) {
        const bool haveNext = (n + 1 < count);
        int ni = i, nj = j, nh = h;
        if (haveNext) f2ijh(start + n + 1, ni, nj, nh);
        const bool aswap = haveNext && (ni != i);

        // prefetch next B half (and A at row-block change) -> alternate buffers
        if (haveNext) {
            load_tile_b(Bb[bbuf ^ 1], nj * 128 + nh * 64, tg);
            if (aswap) load_tile_a(Ab[abuf ^ 1], ni * 128, tg);
            cp_commit();
        }

        const bool diag = (i == j);
        compute_tile(Ab[abuf], Bb[bbuf], wl, lane,
                     diag, j == i + 32, i, h * 64, ra0, ra1, colp);

        // column reduce-scatter: 16 -> 2 per thread, then direct atomics
        if (!diag) {
            int base8 = 0;
            {
                bool hi = (lane >> 2) & 1;
                #pragma unroll
                for (int t = 0; t < 8; ++t) {
                    float send = hi ? colp[t] : colp[t + 8];
                    float r = __shfl_xor_sync(0xffffffffu, send, 4);
                    colp[t] = (hi ? colp[t + 8] : colp[t]) + r;
                }
                base8 += hi ? 8 : 0;
            }
            {
                bool hi = (lane >> 3) & 1;
                #pragma unroll
                for (int t = 0; t < 4; ++t) {
                    float send = hi ? colp[t] : colp[t + 4];
                    float r = __shfl_xor_sync(0xffffffffu, send, 8);
                    colp[t] = (hi ? colp[t + 4] : colp[t]) + r;
                }
                base8 += hi ? 4 : 0;
            }
            {
                bool hi = (lane >> 4) & 1;
                #pragma unroll
                for (int t = 0; t < 2; ++t) {
                    float send = hi ? colp[t] : colp[t + 2];
                    float r = __shfl_xor_sync(0xffffffffu, send, 16);
                    colp[t] = (hi ? colp[t + 2] : colp[t]) + r;
                }
                base8 += hi ? 2 : 0;
            }
            const int m = lane & 3;
            #pragma unroll
            for (int t = 0; t < 2; ++t) {
                int c16 = base8 + t;
                int col = ((c16 >> 1) << 3) + 2 * m + (c16 & 1);
                atomicAdd(&g_partial[j * 128 + h * 64 + col], colp[t]);
            }
        }

        if (!haveNext || ni != i) flush_rows(i, wl, lane, ra0, ra1);

        if (haveNext) {
            cp_wait0();
            grp_bar(grp);       // group-local: next tiles ready, bufs drained
        }
        i = ni; j = nj; h = nh;
        bbuf ^= 1;
        if (aswap) abuf ^= 1;
    }

    // ---- grid barrier: all 148 CTAs resident (one wave) ----
    __syncthreads();
    if (tid == 0) {
        __threadfence();
        atomicAdd(&g_bar, 1u);
        volatile unsigned* p = &g_bar;
        while (*p < (unsigned)GRID) { }
        __threadfence();
    }
    __syncthreads();

    // ---- final phase: per-row loss, then last-block mean ----
    const int c = blockIdx.x;
    if (c < 64 && tid < 128) {
        const int r = c * 128 + tid;
        // loss_r = ln(denom) - s_pos/T = ln2 * (log2(denom) - y_pos)
        float local = lg2f(g_partial[r]) - g_pos[r];
        #pragma unroll
        for (int o = 16; o; o >>= 1) local += __shfl_xor_sync(0xffffffffu, local, o);
        __shared__ float ws[4];
        __shared__ int isLast;
        if ((tid & 31) == 0) ws[tid >> 5] = local;
        __syncwarp();
        asm volatile("bar.sync 3, 128;" ::: "memory");
        if (tid == 0) {
            g_red[c] = ws[0] + ws[1] + ws[2] + ws[3];
            __threadfence();
            unsigned t = atomicAdd(&g_ctr, 1u);
            isLast = (t == 63u);
        }
        asm volatile("bar.sync 3, 128;" ::: "memory");
        if (isLast && tid < 32) {
            __threadfence();
            float t = g_red[tid] + g_red[tid + 32];
            #pragma unroll
            for (int o = 16; o; o >>= 1) t += __shfl_xor_sync(0xffffffffu, t, o);
            if (tid == 0) out[0] = t * (LN2F / (float)NTOT);
        }
    }
}

// ---------------- entry point ----------------
extern "C" void kernel_launch(void* const* d_in, const int* in_sizes, int n_in,
                              void* d_out, int out_size) {
    (void)in_sizes; (void)n_in; (void)out_size;
    const float* xi = (const float*)d_in[0];
    const float* xj = (const float*)d_in[1];

    cudaFuncSetAttribute(gemm_kernel,
                         cudaFuncAttributeMaxDynamicSharedMemorySize, SMEM_BYTES);

    prep_kernel<<<NTOT / 8, 256>>>(xi, xj);
    gemm_kernel<<<GRID, 512, SMEM_BYTES>>>((float*)d_out);
}